// round 8
// baseline (speedup 1.0000x reference)
#include <cuda_runtime.h>
#include <cuda_fp16.h>
#include <cstdint>
#include <cstddef>

#define NROWS 8192
#define DIN   2048
#define DOUT  2048

#define BM 128
#define BN 128
#define BK 32
#define NCHUNK (DIN / BK)          // 64
#define NT_M (NROWS / BM)          // 64
#define NT_N (DOUT / BN)           // 16
#define NSTAGE 3

#define PITCH 40                   // halves per smem row (80B) -> conflict-free ldmatrix
#define A_TILE_BYTES (BM * PITCH * 2)            // 10240
#define B_TILE_BYTES (BN * PITCH * 2)            // 10240
#define A_REGION     (NSTAGE * A_TILE_BYTES)     // 30720
#define B_OFF        A_REGION
#define LUT_OFF      (B_OFF + 2 * B_TILE_BYTES)  // 51200
#define SMEM_TOTAL   (LUT_OFF + 64)              // 51264

#define KWORDS (DIN / 16)          // 128 uint32 code-words per B row

__device__ __align__(16) __half   g_Ah[(size_t)NROWS * DIN];    // 32 MB fp16 A
__device__ __align__(16) uint32_t g_Bc[(size_t)DOUT * KWORDS];  // 1 MB 2-bit codes, row n

static __device__ __forceinline__ uint32_t smem_u32(const void* p) {
    uint32_t a;
    asm("{ .reg .u64 t; cvta.to.shared.u64 t, %1; cvt.u32.u64 %0, t; }" : "=r"(a) : "l"(p));
    return a;
}
static __device__ __forceinline__ uint32_t pack2(float a, float b) {
    __half2 h = __floats2half2_rn(a, b);
    return *reinterpret_cast<uint32_t*>(&h);
}
static __device__ __forceinline__ void cp16(uint32_t dst, const void* src) {
    asm volatile("cp.async.cg.shared.global [%0], [%1], 16;" :: "r"(dst), "l"(src));
}
#define CP_COMMIT() asm volatile("cp.async.commit_group;" ::: "memory")
#define CP_WAIT1()  asm volatile("cp.async.wait_group 1;" ::: "memory")

#define LDSM_X4(r0, r1, r2, r3, addr) \
    asm volatile("ldmatrix.sync.aligned.m8n8.x4.shared.b16 {%0,%1,%2,%3}, [%4];" \
                 : "=r"(r0), "=r"(r1), "=r"(r2), "=r"(r3) : "r"(addr))

#define MMA16816(c, a, b0, b1) \
    asm volatile("mma.sync.aligned.m16n8k16.row.col.f32.f16.f16.f32 " \
                 "{%0,%1,%2,%3}, {%4,%5,%6,%7}, {%8,%9}, {%0,%1,%2,%3};" \
                 : "+f"((c)[0]), "+f"((c)[1]), "+f"((c)[2]), "+f"((c)[3]) \
                 : "r"((a)[0]), "r"((a)[1]), "r"((a)[2]), "r"((a)[3]), \
                   "r"(b0), "r"(b1))

// half encode: code c in {0:0.0, 1:+1.0, 3:-1.0}
static __host__ __device__ __forceinline__ uint32_t code_half(uint32_t c) {
    return ((c & 1u) * 0x3C00u) | ((c & 2u) << 14);
}

// ---------------- prepA: A fp32 -> fp16, row-major ----------------
__global__ __launch_bounds__(256) void prepA_kernel(const float* __restrict__ A) {
    const size_t i = ((size_t)blockIdx.x * 256 + threadIdx.x) * 8;
    const float4* src = reinterpret_cast<const float4*>(A + i);
    float4 f0 = src[0], f1 = src[1];
    uint4 u;
    u.x = pack2(f0.x, f0.y); u.y = pack2(f0.z, f0.w);
    u.z = pack2(f1.x, f1.y); u.w = pack2(f1.z, f1.w);
    *reinterpret_cast<uint4*>(g_Ah + i) = u;
}

// ------- prepB: W[k][n] -> 2-bit codes g_Bc[n][k/16] (transpose in smem) -------
__global__ __launch_bounds__(256) void prepB_kernel(const float* __restrict__ W) {
    __shared__ signed char s[32][33];    // [k][n] sign codes
    const int nb = (int)blockIdx.x % (DOUT / 32);
    const int kb = (int)blockIdx.x / (DOUT / 32);
    const int tx = threadIdx.x & 31, ty = threadIdx.x >> 5;
    #pragma unroll
    for (int j = 0; j < 4; j++) {
        const int kk = ty + j * 8;
        const float w = W[(size_t)(kb * 32 + kk) * DOUT + nb * 32 + tx];
        s[kk][tx] = (signed char)(w > 0.f ? 1 : (w < 0.f ? 3 : 0));
    }
    __syncthreads();
    if (threadIdx.x < 64) {
        const int nn = (int)threadIdx.x >> 1;
        const int half = (int)threadIdx.x & 1;
        uint32_t w = 0;
        #pragma unroll
        for (int j = 0; j < 16; j++)
            w |= ((uint32_t)s[half * 16 + j][nn]) << (2 * j);
        g_Bc[(size_t)(nb * 32 + nn) * KWORDS + kb * 2 + half] = w;
    }
}

// -------------------------------- GEMM --------------------------------
// 128x128 tile, 8 warps (4m x 2n), 3-stage cp.async A, in-smem 2-bit B decode
__global__ __launch_bounds__(256, 2) void gemm_kernel(const float* __restrict__ bias,
                                                      float* __restrict__ out) {
    extern __shared__ __align__(16) unsigned char smem[];
    const uint32_t sbase = smem_u32(smem);
    uint32_t* lut = reinterpret_cast<uint32_t*>(smem + LUT_OFF);

    const int tid = threadIdx.x;
    const int lid = tid & 31;
    const int warp = tid >> 5;
    const int warp_m = warp & 3;
    const int warp_n = warp >> 2;
    const int mt = (int)blockIdx.x & 63;
    const int nt = (int)blockIdx.x >> 6;
    const int m0 = mt * BM, n0 = nt * BN;

    // nibble -> half2 LUT
    if (tid < 16)
        lut[tid] = code_half((uint32_t)tid & 3u) | (code_half(((uint32_t)tid >> 2) & 3u) << 16);

    // ldmatrix frag addresses (stage/buffer 0)
    const int g = lid >> 3, lr = lid & 7;
    uint32_t a_addr[2][2], b_addr[4][2];
    #pragma unroll
    for (int mf = 0; mf < 2; mf++)
        #pragma unroll
        for (int kh = 0; kh < 2; kh++) {
            const int row = warp_m * 32 + mf * 16 + (g & 1) * 8 + lr;
            const int col = kh * 16 + (g >> 1) * 8;
            a_addr[mf][kh] = sbase + (uint32_t)(row * PITCH + col) * 2;
        }
    #pragma unroll
    for (int nf2 = 0; nf2 < 4; nf2++)
        #pragma unroll
        for (int kh = 0; kh < 2; kh++) {
            const int row = warp_n * 64 + nf2 * 16 + (g >> 1) * 8 + lr;
            const int col = kh * 16 + (g & 1) * 8;
            b_addr[nf2][kh] = sbase + B_OFF + (uint32_t)(row * PITCH + col) * 2;
        }

    float c[2][8][4];
    #pragma unroll
    for (int mf = 0; mf < 2; mf++)
        #pragma unroll
        for (int nf = 0; nf < 8; nf++)
            #pragma unroll
            for (int q = 0; q < 4; q++) c[mf][nf][q] = 0.f;

    const __half* gA = g_Ah + (size_t)m0 * DIN;

    // A cp.async: 512 16B-chunks per stage, 2 per thread
    auto issue_A = [&](int stage, int kbase) {
        #pragma unroll
        for (int j = 0; j < 2; j++) {
            const int cidx = tid + j * 256;
            const int row = cidx >> 2, seg = cidx & 3;
            const uint32_t dst = sbase + (uint32_t)stage * A_TILE_BYTES +
                                 (uint32_t)(row * PITCH + seg * 8) * 2;
            cp16(dst, gA + (size_t)row * DIN + kbase + seg * 8);
        }
    };

    // B code fetch + decode: thread -> row tid>>1, word tid&1 (16 halves)
    const int brow = tid >> 1, bword = tid & 1;
    const uint32_t* gBc = g_Bc + (size_t)(n0 + brow) * KWORDS;
    const uint32_t bdst0 = sbase + B_OFF + (uint32_t)(brow * PITCH + bword * 16) * 2;

    auto decode_B = [&](int buf, uint32_t w) {
        uint32_t v[8];
        #pragma unroll
        for (int j = 0; j < 8; j++) v[j] = lut[(w >> (4 * j)) & 15u];
        const uint32_t d = bdst0 + (uint32_t)buf * B_TILE_BYTES;
        *reinterpret_cast<uint4*>((unsigned char*)smem + (d - sbase)) =
            make_uint4(v[0], v[1], v[2], v[3]);
        *reinterpret_cast<uint4*>((unsigned char*)smem + (d - sbase) + 16) =
            make_uint4(v[4], v[5], v[6], v[7]);
    };

    // prologue
    issue_A(0, 0);
    CP_COMMIT();
    issue_A(1, BK);
    CP_COMMIT();
    __syncthreads();                      // lut visible
    decode_B(0, gBc[bword]);              // iter 0's B

    for (int kc = 0; kc < NCHUNK; kc++) {
        const int stage = kc % NSTAGE;
        CP_WAIT1();
        __syncthreads();                  // A stage kc ready; Bs[kc&1] visible
        if (kc + 2 < NCHUNK) issue_A((kc + 2) % NSTAGE, (kc + 2) * BK);
        CP_COMMIT();
        uint32_t wnext = 0;
        if (kc + 1 < NCHUNK) wnext = gBc[(kc + 1) * 2 + bword];

        const uint32_t aoff = (uint32_t)stage * A_TILE_BYTES;
        const uint32_t boff = (uint32_t)(kc & 1) * B_TILE_BYTES;
        #pragma unroll
        for (int kh = 0; kh < 2; kh++) {
            uint32_t a[2][4];
            LDSM_X4(a[0][0], a[0][1], a[0][2], a[0][3], a_addr[0][kh] + aoff);
            LDSM_X4(a[1][0], a[1][1], a[1][2], a[1][3], a_addr[1][kh] + aoff);
            #pragma unroll
            for (int nf2 = 0; nf2 < 4; nf2++) {
                uint32_t b0, b1, b2, b3;
                LDSM_X4(b0, b1, b2, b3, b_addr[nf2][kh] + boff);
                MMA16816(c[0][nf2 * 2 + 0], a[0], b0, b1);
                MMA16816(c[1][nf2 * 2 + 0], a[1], b0, b1);
                MMA16816(c[0][nf2 * 2 + 1], a[0], b2, b3);
                MMA16816(c[1][nf2 * 2 + 1], a[1], b2, b3);
            }
        }
        if (kc + 1 < NCHUNK) decode_B((kc + 1) & 1, wnext);
    }

    // epilogue: bias + sector-aligned float2 stores
    #pragma unroll
    for (int nf = 0; nf < 8; nf++) {
        const int col = n0 + warp_n * 64 + nf * 8 + (lid & 3) * 2;
        const float2 bv = *reinterpret_cast<const float2*>(bias + col);
        #pragma unroll
        for (int mf = 0; mf < 2; mf++) {
            const int r0 = m0 + warp_m * 32 + mf * 16 + (lid >> 2);
            float2 v0 = make_float2(c[mf][nf][0] + bv.x, c[mf][nf][1] + bv.y);
            float2 v1 = make_float2(c[mf][nf][2] + bv.x, c[mf][nf][3] + bv.y);
            *reinterpret_cast<float2*>(out + (size_t)r0 * DOUT + col) = v0;
            *reinterpret_cast<float2*>(out + (size_t)(r0 + 8) * DOUT + col) = v1;
        }
    }
}

extern "C" void kernel_launch(void* const* d_in, const int* in_sizes, int n_in,
                              void* d_out, int out_size) {
    const float* A = (const float*)d_in[0];
    const float* W = (const float*)d_in[1];
    const float* b = (const float*)d_in[2];
    float* out = (float*)d_out;

    cudaFuncSetAttribute(gemm_kernel, cudaFuncAttributeMaxDynamicSharedMemorySize, SMEM_TOTAL);

    prepA_kernel<<<(NROWS * DIN) / (256 * 8), 256>>>(A);
    prepB_kernel<<<(DIN / 32) * (DOUT / 32), 256>>>(W);
    gemm_kernel<<<NT_M * NT_N, 256, SMEM_TOTAL>>>(b, out);
}